// round 2
// baseline (speedup 1.0000x reference)
#include <cuda_runtime.h>
#include <cuda_bf16.h>

#define EPSF 1e-8f
#define LNK  16
#define DST  255
#define TUN  1020
#define MAXS 96          // max gather steps per lane (covers bin count up to 192; ~16 sigma)
#define WPB  8           // warps per block
#define RPW  4           // rows per warp
#define MAXBLK 4096

// Device scratch (no cudaMalloc allowed). Recomputed every call -> deterministic.
__device__ __align__(16) unsigned short g_sched[32 * MAXS];
__device__ int          g_nstep;
__device__ float        g_partials[MAXBLK];
__device__ unsigned int g_count;   // zero-init; reset to 0 by last block each call

// ---------------------------------------------------------------------------
// Setup: build lane-major gather schedule from tunnel_to_link (1 warp).
// Lane L = h*16 + j owns elements of link j's list with rank parity h.
// sched[step*32 + L] = tunnel index (or TUN as pad -> product slot that is 0).
// ---------------------------------------------------------------------------
__global__ void setup_kernel(const int* __restrict__ t2l)
{
    __shared__ int cnt[LNK];
    const int lane = threadIdx.x;
    if (lane < LNK) cnt[lane] = 0;
    for (int i = lane; i < 32 * MAXS; i += 32) g_sched[i] = (unsigned short)TUN;
    __syncwarp();

    int maxstep = 0;
    #pragma unroll 1
    for (int r = 0; r < 32; ++r) {
        const int  t   = r * 32 + lane;
        const bool act = (t < TUN);
        const int  bin = act ? t2l[t] : -1;
        const unsigned peers = __match_any_sync(0xffffffffu, bin);
        const int rank = __popc(peers & ((1u << lane) - 1u));
        const int base = act ? cnt[bin] : 0;
        __syncwarp();
        if (act && rank == 0) cnt[bin] += __popc(peers);   // leader updates count
        __syncwarp();
        if (act) {
            const int pos  = base + rank;
            const int step = pos >> 1;
            if (step < MAXS)
                g_sched[step * 32 + ((pos & 1) << 4) + bin] = (unsigned short)t;
            if (step + 1 > maxstep) maxstep = step + 1;
        }
    }
    #pragma unroll
    for (int off = 16; off; off >>= 1)
        maxstep = max(maxstep, __shfl_xor_sync(0xffffffffu, maxstep, off));
    if (lane == 0) g_nstep = maxstep;
}

// ---------------------------------------------------------------------------
// Main: per row, stage products coalesced into smem, gather per-link sums via
// the schedule, compute stats, deterministic last-block global reduction.
// ---------------------------------------------------------------------------
__global__ __launch_bounds__(256) void loss_main_kernel(
    const float* __restrict__ pred,   // [B,1020]
    const float* __restrict__ dem,    // [B,255]
    const float* __restrict__ clu,    // [B,16]
    const float* __restrict__ caps,   // [16]
    float* __restrict__ out,
    int B, int nb, float invB)
{
    __shared__ __align__(16) unsigned short s_sched[32 * MAXS];  // 6 KB
    __shared__ float s_prod[WPB][TUN + 4];                       // 32 KB, slot TUN.. = 0 pad
    __shared__ float s_inv[LNK];
    __shared__ float s_loss[WPB];
    __shared__ int   s_last;

    const int tid  = threadIdx.x;
    const int warp = tid >> 5;
    const int lane = tid & 31;

    // Stage schedule (as u32 pairs), inverse caps, zero pad slots.
    {
        const unsigned* gs = (const unsigned*)g_sched;
        unsigned* ss = (unsigned*)s_sched;
        #pragma unroll
        for (int i = tid; i < 16 * MAXS; i += 256) ss[i] = gs[i];
    }
    if (tid < LNK) s_inv[tid] = 1.0f / (caps[tid] + EPSF);
    if (lane < 4)  s_prod[warp][TUN + lane] = 0.0f;
    const int nstep = g_nstep;
    __syncthreads();

    const int j = lane & 15;
    float lossw = 0.0f;

    #pragma unroll 1
    for (int r = 0; r < RPW; ++r) {
        const int b = (blockIdx.x * WPB + warp) * RPW + r;
        if (b >= B) break;

        // --- stage products (coalesced loads, conflict-free STS.128) ---
        const float4* __restrict__ pr = (const float4*)(pred + (size_t)b * TUN);
        const float*  __restrict__ dr = dem + (size_t)b * DST;
        #pragma unroll
        for (int it = 0; it < 8; ++it) {
            const int idx = lane + it * 32;
            if (idx < DST) {
                const float4 v = pr[idx];
                const float  d = dr[idx];
                float4 p;
                p.x = v.x * d; p.y = v.y * d; p.z = v.z * d; p.w = v.w * d;
                *(float4*)&s_prod[warp][idx * 4] = p;
            }
        }
        __syncwarp();

        // --- gather: lane accumulates its half of link j's tunnels ---
        float a0 = 0.f, a1 = 0.f, a2 = 0.f, a3 = 0.f;
        int s = 0;
        for (; s + 4 <= nstep; s += 4) {
            const int t0 = s_sched[(s + 0) * 32 + lane];
            const int t1 = s_sched[(s + 1) * 32 + lane];
            const int t2 = s_sched[(s + 2) * 32 + lane];
            const int t3 = s_sched[(s + 3) * 32 + lane];
            a0 += s_prod[warp][t0];
            a1 += s_prod[warp][t1];
            a2 += s_prod[warp][t2];
            a3 += s_prod[warp][t3];
        }
        for (; s < nstep; ++s)
            a0 += s_prod[warp][s_sched[s * 32 + lane]];
        float acc = (a0 + a1) + (a2 + a3);
        __syncwarp();   // protect s_prod before next row's staging

        // combine halves: lanes (j) and (j+16)
        acc += __shfl_xor_sync(0xffffffffu, acc, 16);

        const float u   = acc * s_inv[j];
        const float cur = clu[(size_t)b * LNK + j];

        // 16-lane stats (both halves compute identically)
        float sm = u;
        #pragma unroll
        for (int off = 1; off < 16; off <<= 1)
            sm += __shfl_xor_sync(0xffffffffu, sm, off);
        const float mean = sm * (1.0f / 16.0f);

        const float dv = u - mean;
        float q   = dv * dv;
        float dot = u * cur;
        float mx  = u;
        #pragma unroll
        for (int off = 1; off < 16; off <<= 1) {
            q   += __shfl_xor_sync(0xffffffffu, q, off);
            dot += __shfl_xor_sync(0xffffffffu, dot, off);
            mx   = fmaxf(mx, __shfl_xor_sync(0xffffffffu, mx, off));
        }
        lossw += 0.3f * (q * (1.0f / 15.0f)) + 0.5f * dot + 0.2f * mx;
    }

    if (lane == 0) s_loss[warp] = lossw;
    __syncthreads();

    // block partial + deterministic last-block-done reduction
    if (tid == 0) {
        float t = 0.0f;
        #pragma unroll
        for (int w = 0; w < WPB; ++w) t += s_loss[w];
        g_partials[blockIdx.x] = t;
        __threadfence();
        const unsigned old = atomicAdd(&g_count, 1u);
        s_last = (old == (unsigned)(nb - 1));
    }
    __syncthreads();

    if (s_last) {
        __shared__ float sh[256];
        float v = 0.0f;
        for (int i = tid; i < nb; i += 256) v += __ldcg(&g_partials[i]);
        sh[tid] = v;
        __syncthreads();
        #pragma unroll
        for (int st = 128; st > 0; st >>= 1) {
            if (tid < st) sh[tid] += sh[tid + st];
            __syncthreads();
        }
        if (tid == 0) {
            out[0] = sh[0] * invB;
            g_count = 0;   // reset for next (deterministic) call
        }
    }
}

extern "C" void kernel_launch(void* const* d_in, const int* in_sizes, int n_in,
                              void* d_out, int out_size)
{
    const float* pred = (const float*)d_in[0];
    const float* dem  = (const float*)d_in[1];
    const float* clu  = (const float*)d_in[2];
    const float* caps = (const float*)d_in[3];
    const int*   t2l  = (const int*)d_in[4];
    float* out = (float*)d_out;

    const int B  = in_sizes[0] / TUN;                        // 16384
    int nb = (B + WPB * RPW - 1) / (WPB * RPW);              // 512
    if (nb > MAXBLK) nb = MAXBLK;

    setup_kernel<<<1, 32>>>(t2l);
    loss_main_kernel<<<nb, 256>>>(pred, dem, clu, caps, out, B, nb, 1.0f / (float)B);
}

// round 3
// speedup vs baseline: 1.2973x; 1.2973x over previous
#include <cuda_runtime.h>

#define EPSF 1e-8f
#define LNK  16
#define DST  255
#define TUN  1020
#define NCH  8      // chunks per row
#define CT   128    // tunnels per chunk
#define CD   32     // destinations per chunk
#define ROWS 32     // rows per block
#define THR  256

#define CP4(dst, src) asm volatile("cp.async.ca.shared.global [%0], [%1], 4;" :: "r"(dst), "l"(src))
#define CP_COMMIT()   asm volatile("cp.async.commit_group;")
#define CP_WAIT(n)    asm volatile("cp.async.wait_group %0;" :: "n"(n))

__device__ float    g_partials[1024];
__device__ unsigned g_count;   // zero-init; last block resets to 0 (deterministic)

__device__ __forceinline__ unsigned smem_u32(const void* p) {
    return (unsigned)__cvta_generic_to_shared(p);
}

__global__ __launch_bounds__(THR, 4) void loss_kernel(
    const float* __restrict__ pred,   // [B,1020]
    const float* __restrict__ dem,    // [B,255]
    const float* __restrict__ clu,    // [B,16]
    const float* __restrict__ caps,   // [16]
    const int*   __restrict__ t2l,    // [1020]
    float* __restrict__ out,
    int B, int nb, float invB)
{
    __shared__ float s_prod[2][CT * 33];   // [tunnel_local][row], stride 33 -> conflict-free
    __shared__ float s_demand[2][CD * 33]; // [dst_local][row]
    __shared__ float s_nl[ROWS * 17];      // per-row link traffic
    __shared__ unsigned char s_sched[NCH * CT];  // chunk-local tunnel ids sorted by bin
    __shared__ int   s_off[NCH][17];       // per-chunk bin offsets (exclusive scan)
    __shared__ int   s_cur[NCH][17];
    __shared__ float s_inv[LNK];
    __shared__ float s_loss[8];
    __shared__ float s_fin[THR];
    __shared__ int   s_last;

    const int tid  = threadIdx.x;
    const int warp = tid >> 5;
    const int lane = tid & 31;
    const int base = blockIdx.x * ROWS;

    // ---------- kick prefetch of chunk 0 immediately (hide DRAM latency) ----------
    {
        const unsigned pb = smem_u32(&s_prod[0][0]);
        const unsigned db = smem_u32(&s_demand[0][0]);
        #pragma unroll
        for (int q = 0; q < 4; ++q) {
            const int r = warp + q * 8;
            const int brow = base + r;
            if (brow < B) {
                const float* src = pred + (size_t)brow * TUN;
                #pragma unroll
                for (int p = 0; p < 4; ++p) {
                    const int tl = p * 32 + lane;
                    CP4(pb + (unsigned)(tl * 33 + r) * 4u, src + tl);
                }
                CP4(db + (unsigned)(lane * 33 + r) * 4u,
                    dem + (size_t)brow * DST + lane);
            }
        }
        CP_COMMIT();
    }

    // ---------- in-block schedule build: warp c sorts chunk c by bin ----------
    {
        const int c = warp;
        if (lane < 17) s_cur[c][lane] = 0;     // use s_cur as counts first
        int bins[4];
        #pragma unroll
        for (int q = 0; q < 4; ++q) {
            const int t = c * CT + q * 32 + lane;
            bins[q] = (t < TUN) ? t2l[t] : 16;
        }
        __syncwarp();
        #pragma unroll
        for (int q = 0; q < 4; ++q) {          // pass 1: counts
            const unsigned peers = __match_any_sync(0xffffffffu, bins[q]);
            const int rank = __popc(peers & ((1u << lane) - 1u));
            if (rank == 0) s_cur[c][bins[q]] += __popc(peers);
            __syncwarp();
        }
        if (lane < 17) {                       // exclusive scan (tiny)
            int o = 0;
            for (int i = 0; i < lane; ++i) o += s_cur[c][i];
            s_off[c][lane] = o;
        }
        __syncwarp();
        if (lane < 17) s_cur[c][lane] = s_off[c][lane];
        __syncwarp();
        #pragma unroll
        for (int q = 0; q < 4; ++q) {          // pass 2: stable placement
            const unsigned peers = __match_any_sync(0xffffffffu, bins[q]);
            const int rank = __popc(peers & ((1u << lane) - 1u));
            const int bse  = s_cur[c][bins[q]];
            __syncwarp();
            if (rank == 0) s_cur[c][bins[q]] = bse + __popc(peers);
            __syncwarp();
            if (bins[q] < 16)
                s_sched[c * CT + bse + rank] = (unsigned char)(q * 32 + lane);
        }
    }
    if (tid < LNK) s_inv[tid] = 1.0f / (caps[tid] + EPSF);

    // ---------- main pipeline: prefetch(c+1) overlapped with gather(c) ----------
    float acc0 = 0.0f, acc1 = 0.0f;   // warp owns bins 2*warp, 2*warp+1 (all 32 rows)

    #pragma unroll 1
    for (int c = 0; c < NCH; ++c) {
        if (c < NCH - 1) {
            const int cn = c + 1;
            const int bsel = cn & 1;
            const unsigned pb = smem_u32(&s_prod[bsel][0]);
            const unsigned db = smem_u32(&s_demand[bsel][0]);
            #pragma unroll
            for (int q = 0; q < 4; ++q) {
                const int r = warp + q * 8;
                const int brow = base + r;
                if (brow < B) {
                    const float* src = pred + (size_t)brow * TUN + cn * CT;
                    #pragma unroll
                    for (int p = 0; p < 4; ++p) {
                        const int tl = p * 32 + lane;
                        if (cn * CT + tl < TUN)
                            CP4(pb + (unsigned)(tl * 33 + r) * 4u, src + tl);
                    }
                    if (cn * CD + lane < DST)
                        CP4(db + (unsigned)(lane * 33 + r) * 4u,
                            dem + (size_t)brow * DST + cn * CD + lane);
                }
            }
            CP_COMMIT();
            CP_WAIT(1);
        } else {
            CP_WAIT(0);
        }
        __syncthreads();   // chunk c staged for all warps; schedule build done (c==0)

        const float* __restrict__ P = s_prod[c & 1];
        const float* __restrict__ D = s_demand[c & 1];
        const int lo  = s_off[c][2 * warp];
        const int mid = s_off[c][2 * warp + 1];
        const int hi  = s_off[c][2 * warp + 2];
        const unsigned char* sc = &s_sched[c * CT];

        for (int k = lo; k < mid; ++k) {
            const int t = sc[k];                               // warp-uniform
            acc0 = fmaf(P[t * 33 + lane], D[(t >> 2) * 33 + lane], acc0);
        }
        for (int k = mid; k < hi; ++k) {
            const int t = sc[k];
            acc1 = fmaf(P[t * 33 + lane], D[(t >> 2) * 33 + lane], acc1);
        }
        __syncthreads();   // buffer (c&1) free for chunk c+2
    }

    // ---------- per-row link traffic -> stats ----------
    s_nl[lane * 17 + 2 * warp]     = acc0;   // banks (17*lane + j) % 32: conflict-free
    s_nl[lane * 17 + 2 * warp + 1] = acc1;
    __syncthreads();

    float lsum = 0.0f;
    #pragma unroll
    for (int p = 0; p < 2; ++p) {
        const int r = p * 16 + warp * 2 + (lane >> 4);   // 16 rows per pass
        const int j = lane & 15;
        const int brow = base + r;
        const float u   = s_nl[r * 17 + j] * s_inv[j];
        const float cur = (brow < B) ? clu[(size_t)brow * LNK + j] : 0.0f;

        float sm = u;
        #pragma unroll
        for (int off = 1; off < 16; off <<= 1)
            sm += __shfl_xor_sync(0xffffffffu, sm, off);
        const float mean = sm * (1.0f / 16.0f);

        const float dv = u - mean;
        float q2  = dv * dv;
        float dot = u * cur;
        float mx  = u;
        #pragma unroll
        for (int off = 1; off < 16; off <<= 1) {
            q2  += __shfl_xor_sync(0xffffffffu, q2, off);
            dot += __shfl_xor_sync(0xffffffffu, dot, off);
            mx   = fmaxf(mx, __shfl_xor_sync(0xffffffffu, mx, off));
        }
        if (j == 0 && brow < B)
            lsum += 0.3f * (q2 * (1.0f / 15.0f)) + 0.5f * dot + 0.2f * mx;
    }
    lsum += __shfl_xor_sync(0xffffffffu, lsum, 16);
    if (lane == 0) s_loss[warp] = lsum;
    __syncthreads();

    // ---------- deterministic single-launch global reduction ----------
    if (tid == 0) {
        float t = 0.0f;
        #pragma unroll
        for (int w = 0; w < 8; ++w) t += s_loss[w];
        g_partials[blockIdx.x] = t;
        __threadfence();
        const unsigned old = atomicAdd(&g_count, 1u);
        s_last = (old == (unsigned)(nb - 1));
    }
    __syncthreads();

    if (s_last) {
        float v = 0.0f;
        for (int i = tid; i < nb; i += THR) v += __ldcg(&g_partials[i]);
        s_fin[tid] = v;
        __syncthreads();
        #pragma unroll
        for (int st = 128; st > 0; st >>= 1) {
            if (tid < st) s_fin[tid] += s_fin[tid + st];
            __syncthreads();
        }
        if (tid == 0) {
            out[0] = s_fin[0] * invB;
            g_count = 0;
        }
    }
}

extern "C" void kernel_launch(void* const* d_in, const int* in_sizes, int n_in,
                              void* d_out, int out_size)
{
    const float* pred = (const float*)d_in[0];
    const float* dem  = (const float*)d_in[1];
    const float* clu  = (const float*)d_in[2];
    const float* caps = (const float*)d_in[3];
    const int*   t2l  = (const int*)d_in[4];
    float* out = (float*)d_out;

    const int B  = in_sizes[0] / TUN;          // 16384
    int nb = (B + ROWS - 1) / ROWS;            // 512
    if (nb > 1024) nb = 1024;

    loss_kernel<<<nb, THR>>>(pred, dem, clu, caps, t2l, out, B, nb, 1.0f / (float)B);
}

// round 4
// speedup vs baseline: 1.5939x; 1.2286x over previous
#include <cuda_runtime.h>

#define EPSF 1e-8f
#define LNK  16
#define DST  255
#define TUN  1020
#define NCH  8          // chunks per row (128 tunnels each)
#define ROWS 28         // rows per block -> 586 blocks ~= 4 per SM, balanced
#define RPAD 29         // odd row stride -> conflict-free both directions
#define PLW  (32*RPAD)  // 928 words per plane (928 % 32 == 0)
#define PLB  (PLW*4)    // 3712 bytes per plane
#define THR  256

__device__ float    g_partials[1024];
__device__ unsigned g_count;   // zero-init; last block resets (deterministic)

__global__ __launch_bounds__(THR, 4) void loss_kernel(
    const float* __restrict__ pred,   // [B,1020]
    const float* __restrict__ dem,    // [B,255]
    const float* __restrict__ clu,    // [B,16]
    const float* __restrict__ caps,   // [16]
    const int*   __restrict__ t2l,    // [1020]
    float* __restrict__ out,
    int B, int nb, float invB)
{
    __shared__ float s_pl[2][4][PLW];            // 29696 B product planes
    __shared__ unsigned short s_sched[NCH*128];  // byte offsets, sorted by bin
    __shared__ int   s_off[NCH][17];
    __shared__ int   s_cur[NCH][17];
    __shared__ float s_nl[32*17];
    __shared__ float s_inv[LNK];
    __shared__ float s_loss[8];
    __shared__ float s_fin[THR];
    __shared__ int   s_last;

    const int tid  = threadIdx.x;
    const int warp = tid >> 5;
    const int lane = tid & 31;
    const int base = blockIdx.x * ROWS;

    // rows this warp stages: r = warp + 8q, q = 0..3
    float4 rv[4]; float dv[4];

    // ---------------- prologue: LDG chunk 0 into registers ----------------
    {
        const int gg = lane;                       // global float4 group (= dest)
        #pragma unroll
        for (int q = 0; q < 4; ++q) {
            const int r = warp + q * 8;
            const int brow = base + r;
            const bool ok = (r < ROWS) && (brow < B) && (gg < DST);
            rv[q] = ok ? ((const float4*)pred)[(size_t)brow * DST + gg]
                       : make_float4(0.f, 0.f, 0.f, 0.f);
            dv[q] = ok ? dem[(size_t)brow * DST + gg] : 0.0f;
        }
    }

    // ---------------- in-block schedule: warp c sorts chunk c by bin -------
    {
        const int c = warp;
        if (lane < 17) s_cur[c][lane] = 0;
        int bins[4];
        #pragma unroll
        for (int q = 0; q < 4; ++q) {
            const int t = c * 128 + q * 32 + lane;
            bins[q] = (t < TUN) ? t2l[t] : 16;
        }
        __syncwarp();
        #pragma unroll
        for (int q = 0; q < 4; ++q) {            // counts
            const unsigned peers = __match_any_sync(0xffffffffu, bins[q]);
            const int rank = __popc(peers & ((1u << lane) - 1u));
            if (rank == 0) s_cur[c][bins[q]] += __popc(peers);
            __syncwarp();
        }
        if (lane < 17) {                          // exclusive scan
            int o = 0;
            for (int i = 0; i < lane; ++i) o += s_cur[c][i];
            s_off[c][lane] = o;
        }
        __syncwarp();
        if (lane < 17) s_cur[c][lane] = s_off[c][lane];
        __syncwarp();
        #pragma unroll
        for (int q = 0; q < 4; ++q) {            // stable placement -> byte offsets
            const unsigned peers = __match_any_sync(0xffffffffu, bins[q]);
            const int rank = __popc(peers & ((1u << lane) - 1u));
            const int bse  = s_cur[c][bins[q]];
            __syncwarp();
            if (rank == 0) s_cur[c][bins[q]] = bse + __popc(peers);
            __syncwarp();
            if (bins[q] < 16) {
                const int t = c * 128 + q * 32 + lane;
                const unsigned off = (unsigned)(t & 3) * PLB
                                   + (unsigned)((t >> 2) & 31) * (RPAD * 4);
                s_sched[c * 128 + bse + rank] = (unsigned short)off;
            }
        }
    }
    if (tid < LNK) s_inv[tid] = 1.0f / (caps[tid] + EPSF);

    // ---------------- STS chunk 0 (products) ------------------------------
    #pragma unroll
    for (int q = 0; q < 4; ++q) {
        const int r = warp + q * 8;
        if (r < ROWS) {
            s_pl[0][0][lane * RPAD + r] = rv[q].x * dv[q];
            s_pl[0][1][lane * RPAD + r] = rv[q].y * dv[q];
            s_pl[0][2][lane * RPAD + r] = rv[q].z * dv[q];
            s_pl[0][3][lane * RPAD + r] = rv[q].w * dv[q];
        }
    }
    __syncthreads();

    // ---------------- main loop: LDG(c+1) | gather(c) | STS(c+1) ----------
    float acc0 = 0.0f, acc1 = 0.0f;   // warp owns bins 2w, 2w+1 for all rows

    #pragma unroll 1
    for (int c = 0; c < NCH; ++c) {
        if (c < NCH - 1) {
            const int gg = (c + 1) * 32 + lane;
            #pragma unroll
            for (int q = 0; q < 4; ++q) {
                const int r = warp + q * 8;
                const int brow = base + r;
                const bool ok = (r < ROWS) && (brow < B) && (gg < DST);
                rv[q] = ok ? ((const float4*)pred)[(size_t)brow * DST + gg]
                           : make_float4(0.f, 0.f, 0.f, 0.f);
                dv[q] = ok ? dem[(size_t)brow * DST + gg] : 0.0f;
            }
        }

        // gather chunk c (lane = row, warp-uniform offsets -> 1 wavefront/LDS)
        {
            const char* bp = (const char*)(&s_pl[c & 1][0][0]) + (lane << 2);
            const unsigned short* sc = &s_sched[c * 128];
            const int lo  = s_off[c][2 * warp];
            const int mid = s_off[c][2 * warp + 1];
            const int hi  = s_off[c][2 * warp + 2];
            #pragma unroll 2
            for (int k = lo; k < mid; ++k)
                acc0 += *(const float*)(bp + sc[k]);
            #pragma unroll 2
            for (int k = mid; k < hi; ++k)
                acc1 += *(const float*)(bp + sc[k]);
        }

        if (c < NCH - 1) {
            const int nbuf = (c + 1) & 1;
            #pragma unroll
            for (int q = 0; q < 4; ++q) {
                const int r = warp + q * 8;
                if (r < ROWS) {
                    s_pl[nbuf][0][lane * RPAD + r] = rv[q].x * dv[q];
                    s_pl[nbuf][1][lane * RPAD + r] = rv[q].y * dv[q];
                    s_pl[nbuf][2][lane * RPAD + r] = rv[q].z * dv[q];
                    s_pl[nbuf][3][lane * RPAD + r] = rv[q].w * dv[q];
                }
            }
        }
        __syncthreads();
    }

    // ---------------- stats ------------------------------------------------
    if (lane < ROWS) {
        s_nl[lane * 17 + 2 * warp]     = acc0;
        s_nl[lane * 17 + 2 * warp + 1] = acc1;
    }
    __syncthreads();

    float lsum = 0.0f;
    #pragma unroll
    for (int p = 0; p < 2; ++p) {
        const int r = p * 16 + warp * 2 + (lane >> 4);
        const int j = lane & 15;
        const int brow = base + r;
        const bool rok = (r < ROWS) && (brow < B);
        const float u   = rok ? s_nl[r * 17 + j] * s_inv[j] : 0.0f;
        const float cur = rok ? clu[(size_t)brow * LNK + j] : 0.0f;

        float sm = u;
        #pragma unroll
        for (int off = 1; off < 16; off <<= 1)
            sm += __shfl_xor_sync(0xffffffffu, sm, off);
        const float mean = sm * (1.0f / 16.0f);

        const float dv2 = u - mean;
        float q2  = dv2 * dv2;
        float dot = u * cur;
        float mx  = u;
        #pragma unroll
        for (int off = 1; off < 16; off <<= 1) {
            q2  += __shfl_xor_sync(0xffffffffu, q2, off);
            dot += __shfl_xor_sync(0xffffffffu, dot, off);
            mx   = fmaxf(mx, __shfl_xor_sync(0xffffffffu, mx, off));
        }
        if (j == 0 && rok)
            lsum += 0.3f * (q2 * (1.0f / 15.0f)) + 0.5f * dot + 0.2f * mx;
    }
    lsum += __shfl_xor_sync(0xffffffffu, lsum, 16);
    if (lane == 0) s_loss[warp] = lsum;
    __syncthreads();

    // ---------------- deterministic single-launch reduction ----------------
    if (tid == 0) {
        float t = 0.0f;
        #pragma unroll
        for (int w = 0; w < 8; ++w) t += s_loss[w];
        g_partials[blockIdx.x] = t;
        __threadfence();
        const unsigned old = atomicAdd(&g_count, 1u);
        s_last = (old == (unsigned)(nb - 1));
    }
    __syncthreads();

    if (s_last) {
        float v = 0.0f;
        for (int i = tid; i < nb; i += THR) v += __ldcg(&g_partials[i]);
        s_fin[tid] = v;
        __syncthreads();
        #pragma unroll
        for (int st = 128; st > 0; st >>= 1) {
            if (tid < st) s_fin[tid] += s_fin[tid + st];
            __syncthreads();
        }
        if (tid == 0) {
            out[0] = s_fin[0] * invB;
            g_count = 0;
        }
    }
}

extern "C" void kernel_launch(void* const* d_in, const int* in_sizes, int n_in,
                              void* d_out, int out_size)
{
    const float* pred = (const float*)d_in[0];
    const float* dem  = (const float*)d_in[1];
    const float* clu  = (const float*)d_in[2];
    const float* caps = (const float*)d_in[3];
    const int*   t2l  = (const int*)d_in[4];
    float* out = (float*)d_out;

    const int B  = in_sizes[0] / TUN;            // 16384
    int nb = (B + ROWS - 1) / ROWS;              // 586
    if (nb > 1024) nb = 1024;

    loss_kernel<<<nb, THR>>>(pred, dem, clu, caps, t2l, out, B, nb, 1.0f / (float)B);
}

// round 5
// speedup vs baseline: 1.9024x; 1.1936x over previous
#include <cuda_runtime.h>

#define EPSF 1e-8f
#define LNK   16
#define DST   255
#define TUN   1020
#define NCH   8
#define PAIRS 28          // row pairs per block
#define ROWS  56
#define SSTR  58          // words per slot (28 pairs * 2 + 2 pad)
#define PLW   (32*SSTR)   // 1856 words per plane
#define ZW    (4*PLW)     // zero region start (word index 7424)
#define ZBYTE (ZW*4)      // 29696, fits u16
#define SCHW  144         // padded schedule entries per chunk
#define THR   512

__device__ float    g_partials[512];
__device__ unsigned g_count;   // zero-init; last block resets (deterministic)

__device__ __forceinline__ unsigned long long lds64(unsigned a) {
    unsigned long long v;
    asm volatile("ld.shared.b64 %0, [%1];" : "=l"(v) : "r"(a));
    return v;
}
__device__ __forceinline__ unsigned long long addx2(unsigned long long a,
                                                    unsigned long long b) {
    unsigned long long r;
    asm("add.rn.f32x2 %0, %1, %2;" : "=l"(r) : "l"(a), "l"(b));
    return r;
}

__global__ __launch_bounds__(THR, 2) void loss_kernel(
    const float* __restrict__ pred,   // [B,1020]
    const float* __restrict__ dem,    // [B,255]
    const float* __restrict__ clu,    // [B,16]
    const float* __restrict__ caps,   // [16]
    const int*   __restrict__ t2l,    // [1020]
    float* __restrict__ out,
    int B, int nb, float invB)
{
    __shared__ float s_pl[ZW + 64];                 // planes + 256B zero region
    __shared__ unsigned short s_sched[NCH * SCHW];  // padded, byte offsets
    __shared__ int   s_off[NCH][17];                // padded exclusive offsets
    __shared__ int   s_cur[NCH][17];
    __shared__ float s_nl[ROWS * 17];
    __shared__ float s_inv[LNK];
    __shared__ float s_loss[16];
    __shared__ float s_fin[THR];
    __shared__ int   s_last;

    const int tid  = threadIdx.x;
    const int warp = tid >> 5;          // 0..15
    const int lane = tid & 31;
    const int base = blockIdx.x * ROWS;
    const unsigned pl32 = (unsigned)__cvta_generic_to_shared(s_pl);

    // pairs this warp stages: pr = warp (+16 if warp<12)
    float4 ra[2], rb[2];
    float  da[2], db[2];

    // ------------- LDG chunk 0 for this warp's pairs ----------------------
    #pragma unroll
    for (int u = 0; u < 2; ++u) {
        const int pr = warp + 16 * u;
        const int r0 = base + pr, r1 = base + pr + PAIRS;
        const bool okp = (pr < PAIRS);
        const bool o0 = okp && (r0 < B), o1 = okp && (r1 < B);
        const int gg = lane;
        ra[u] = o0 ? ((const float4*)pred)[(size_t)r0 * DST + gg] : make_float4(0,0,0,0);
        rb[u] = o1 ? ((const float4*)pred)[(size_t)r1 * DST + gg] : make_float4(0,0,0,0);
        da[u] = o0 ? dem[(size_t)r0 * DST + gg] : 0.0f;
        db[u] = o1 ? dem[(size_t)r1 * DST + gg] : 0.0f;
    }

    // ------------- schedule build: warp c (<8) sorts chunk c --------------
    if (warp < 8) {
        const int c = warp;
        if (lane < 17) s_cur[c][lane] = 0;
        int bins[4];
        #pragma unroll
        for (int q = 0; q < 4; ++q) {
            const int t = c * 128 + q * 32 + lane;
            bins[q] = (t < TUN) ? t2l[t] : 16;
        }
        __syncwarp();
        #pragma unroll
        for (int q = 0; q < 4; ++q) {                       // counts
            const unsigned peers = __match_any_sync(0xffffffffu, bins[q]);
            const int rank = __popc(peers & ((1u << lane) - 1u));
            if (rank == 0) s_cur[c][bins[q]] += __popc(peers);
            __syncwarp();
        }
        if (lane < 17) {                                    // padded excl scan
            int o = 0;
            for (int i = 0; i < lane; ++i) o += (s_cur[c][i] + 1) & ~1;
            s_off[c][lane] = o;
        }
        __syncwarp();
        for (int i = lane; i < SCHW; i += 32)               // prefill dummies
            s_sched[c * SCHW + i] = (unsigned short)ZBYTE;
        if (lane < 17) s_cur[c][lane] = s_off[c][lane];
        __syncwarp();
        #pragma unroll
        for (int q = 0; q < 4; ++q) {                       // stable placement
            const unsigned peers = __match_any_sync(0xffffffffu, bins[q]);
            const int rank = __popc(peers & ((1u << lane) - 1u));
            const int bse  = s_cur[c][bins[q]];
            __syncwarp();
            if (rank == 0) s_cur[c][bins[q]] = bse + __popc(peers);
            __syncwarp();
            if (bins[q] < 16) {
                const int tl = q * 32 + lane;               // chunk-local id
                const unsigned off = (unsigned)(tl & 3) * (PLW * 4)
                                   + (unsigned)(tl >> 2) * (SSTR * 4);
                s_sched[c * SCHW + bse + rank] = (unsigned short)off;
            }
        }
    } else if (warp == 8) {
        for (int i = lane; i < 64; i += 32) s_pl[ZW + i] = 0.0f;  // zero region
    }
    if (tid < LNK) s_inv[tid] = 1.0f / (caps[tid] + EPSF);

    // ------------- STS chunk 0 --------------------------------------------
    #pragma unroll
    for (int u = 0; u < 2; ++u) {
        const int pr = warp + 16 * u;
        if (pr < PAIRS) {
            const int wbase = lane * SSTR + pr * 2;
            ((float2*)s_pl)[(0 * PLW + wbase) >> 1] = make_float2(ra[u].x * da[u], rb[u].x * db[u]);
            ((float2*)s_pl)[(1 * PLW + wbase) >> 1] = make_float2(ra[u].y * da[u], rb[u].y * db[u]);
            ((float2*)s_pl)[(2 * PLW + wbase) >> 1] = make_float2(ra[u].z * da[u], rb[u].z * db[u]);
            ((float2*)s_pl)[(3 * PLW + wbase) >> 1] = make_float2(ra[u].w * da[u], rb[u].w * db[u]);
        }
    }
    __syncthreads();

    // ------------- main loop: LDG(c+1) | gather(c) | STS(c+1) -------------
    unsigned long long acc0 = 0ull, acc1 = 0ull;     // packed f32x2 accumulators
    const unsigned lbase = pl32 + (unsigned)(lane << 3);

    #pragma unroll 1
    for (int c = 0; c < NCH; ++c) {
        if (c < NCH - 1) {
            const int gg = (c + 1) * 32 + lane;
            #pragma unroll
            for (int u = 0; u < 2; ++u) {
                const int pr = warp + 16 * u;
                const int r0 = base + pr, r1 = base + pr + PAIRS;
                const bool okp = (pr < PAIRS) && (gg < DST);
                const bool o0 = okp && (r0 < B), o1 = okp && (r1 < B);
                ra[u] = o0 ? ((const float4*)pred)[(size_t)r0 * DST + gg] : make_float4(0,0,0,0);
                rb[u] = o1 ? ((const float4*)pred)[(size_t)r1 * DST + gg] : make_float4(0,0,0,0);
                da[u] = o0 ? dem[(size_t)r0 * DST + gg] : 0.0f;
                db[u] = o1 ? dem[(size_t)r1 * DST + gg] : 0.0f;
            }
        }

        // gather chunk c: warp owns bin = warp; entries padded to even count
        {
            const unsigned short* sc = &s_sched[c * SCHW];
            int k = s_off[c][warp];
            const int hi = s_off[c][warp + 1];
            #pragma unroll 2
            for (; k < hi; k += 2) {
                const unsigned o0 = sc[k];
                const unsigned o1 = sc[k + 1];
                acc0 = addx2(acc0, lds64(lbase + o0));
                acc1 = addx2(acc1, lds64(lbase + o1));
            }
        }
        __syncthreads();                 // gather(c) done -> planes reusable

        if (c < NCH - 1) {
            #pragma unroll
            for (int u = 0; u < 2; ++u) {
                const int pr = warp + 16 * u;
                if (pr < PAIRS) {
                    const int wbase = lane * SSTR + pr * 2;
                    ((float2*)s_pl)[(0 * PLW + wbase) >> 1] = make_float2(ra[u].x * da[u], rb[u].x * db[u]);
                    ((float2*)s_pl)[(1 * PLW + wbase) >> 1] = make_float2(ra[u].y * da[u], rb[u].y * db[u]);
                    ((float2*)s_pl)[(2 * PLW + wbase) >> 1] = make_float2(ra[u].z * da[u], rb[u].z * db[u]);
                    ((float2*)s_pl)[(3 * PLW + wbase) >> 1] = make_float2(ra[u].w * da[u], rb[u].w * db[u]);
                }
            }
            __syncthreads();
        }
    }

    // ------------- per-(row,bin) traffic -> stats --------------------------
    {
        const unsigned long long t = addx2(acc0, acc1);
        const float lo = __uint_as_float((unsigned)(t & 0xffffffffull));
        const float hi = __uint_as_float((unsigned)(t >> 32));
        if (lane < PAIRS) {
            s_nl[lane * 17 + warp] = lo;              // row = lane
            s_nl[(lane + PAIRS) * 17 + warp] = hi;    // row = lane + 28
        }
    }
    __syncthreads();

    float lsum = 0.0f;
    #pragma unroll
    for (int p = 0; p < 2; ++p) {
        const int rid = p * 32 + (warp << 1) + (lane >> 4);
        const int j = lane & 15;
        const int brow = base + rid;
        const bool rok = (rid < ROWS) && (brow < B);
        const float u   = rok ? s_nl[rid * 17 + j] * s_inv[j] : 0.0f;
        const float cur = rok ? clu[(size_t)brow * LNK + j] : 0.0f;

        float sm = u;
        #pragma unroll
        for (int off = 1; off < 16; off <<= 1)
            sm += __shfl_xor_sync(0xffffffffu, sm, off);
        const float mean = sm * (1.0f / 16.0f);

        const float dv = u - mean;
        float q2  = dv * dv;
        float dot = u * cur;
        float mx  = u;
        #pragma unroll
        for (int off = 1; off < 16; off <<= 1) {
            q2  += __shfl_xor_sync(0xffffffffu, q2, off);
            dot += __shfl_xor_sync(0xffffffffu, dot, off);
            mx   = fmaxf(mx, __shfl_xor_sync(0xffffffffu, mx, off));
        }
        if (j == 0 && rok)
            lsum += 0.3f * (q2 * (1.0f / 15.0f)) + 0.5f * dot + 0.2f * mx;
    }
    lsum += __shfl_xor_sync(0xffffffffu, lsum, 16);
    if (lane == 0) s_loss[warp] = lsum;
    __syncthreads();

    // ------------- deterministic single-launch reduction -------------------
    if (tid == 0) {
        float t = 0.0f;
        #pragma unroll
        for (int w = 0; w < 16; ++w) t += s_loss[w];
        g_partials[blockIdx.x] = t;
        __threadfence();
        const unsigned old = atomicAdd(&g_count, 1u);
        s_last = (old == (unsigned)(nb - 1));
    }
    __syncthreads();

    if (s_last) {
        float v = 0.0f;
        for (int i = tid; i < nb; i += THR) v += __ldcg(&g_partials[i]);
        s_fin[tid] = v;
        __syncthreads();
        #pragma unroll
        for (int st = 256; st > 0; st >>= 1) {
            if (tid < st) s_fin[tid] += s_fin[tid + st];
            __syncthreads();
        }
        if (tid == 0) {
            out[0] = s_fin[0] * invB;
            g_count = 0;
        }
    }
}

extern "C" void kernel_launch(void* const* d_in, const int* in_sizes, int n_in,
                              void* d_out, int out_size)
{
    const float* pred = (const float*)d_in[0];
    const float* dem  = (const float*)d_in[1];
    const float* clu  = (const float*)d_in[2];
    const float* caps = (const float*)d_in[3];
    const int*   t2l  = (const int*)d_in[4];
    float* out = (float*)d_out;

    const int B  = in_sizes[0] / TUN;           // 16384
    int nb = (B + ROWS - 1) / ROWS;             // 293
    if (nb > 512) nb = 512;

    loss_kernel<<<nb, THR>>>(pred, dem, clu, caps, t2l, out, B, nb, 1.0f / (float)B);
}